// round 15
// baseline (speedup 1.0000x reference)
#include <cuda_runtime.h>
#include <cuda_fp16.h>
#include <math.h>
#include <stdint.h>

#define EMBED    768
#define SEQ_T    2048
#define BATCH    4
#define HEADS    12
#define HD       64
#define M_ROWS   (BATCH * SEQ_T)     /* 8192 */
#define QKV_N    (3 * EMBED)         /* 2304 */
#define K2       (EMBED / 2)         /* 384 u32 per k-row */

/* scratch — all fp16 payloads stored as uint32 (half2) */
__device__ uint32_t g_qkv  [(size_t)M_ROWS * (QKV_N / 2)];
__device__ uint32_t g_attn [(size_t)M_ROWS * (EMBED / 2)];
__device__ uint32_t g_xh   [(size_t)M_ROWS * K2];
__device__ uint32_t g_wqkvT[(size_t)QKV_N * K2];
__device__ uint32_t g_wprjT[(size_t)EMBED * K2];

/* ---------------- helpers ---------------- */
__device__ __forceinline__ uint32_t pack_h2(float lo, float hi) {
    __half2 h = __floats2half2_rn(lo, hi);
    return *(uint32_t*)&h;
}
__device__ __forceinline__ uint32_t h2ex2(uint32_t x) {
    uint32_t r;
    asm("ex2.approx.f16x2 %0, %1;" : "=r"(r) : "r"(x));
    return r;
}
__device__ __forceinline__ void mma16(float c[4], const uint32_t a[4], const uint32_t b0, const uint32_t b1) {
    asm volatile(
        "mma.sync.aligned.m16n8k16.row.col.f32.f16.f16.f32 "
        "{%0,%1,%2,%3}, {%4,%5,%6,%7}, {%8,%9}, {%0,%1,%2,%3};"
        : "+f"(c[0]), "+f"(c[1]), "+f"(c[2]), "+f"(c[3])
        : "r"(a[0]), "r"(a[1]), "r"(a[2]), "r"(a[3]), "r"(b0), "r"(b1));
}
__device__ __forceinline__ void ldsm4(uint32_t r[4], uint32_t saddr) {
    asm volatile(
        "ldmatrix.sync.aligned.m8n8.x4.shared.b16 {%0,%1,%2,%3}, [%4];"
        : "=r"(r[0]), "=r"(r[1]), "=r"(r[2]), "=r"(r[3]) : "r"(saddr));
}
__device__ __forceinline__ void ldsm4t(uint32_t r[4], uint32_t saddr) {
    asm volatile(
        "ldmatrix.sync.aligned.m8n8.x4.trans.shared.b16 {%0,%1,%2,%3}, [%4];"
        : "=r"(r[0]), "=r"(r[1]), "=r"(r[2]), "=r"(r[3]) : "r"(saddr));
}
__device__ __forceinline__ void cpa16(uint32_t dst, const void* src) {
    asm volatile("cp.async.ca.shared.global [%0], [%1], 16;"
                 :: "r"(dst), "l"(src));
}
#define CP_COMMIT() asm volatile("cp.async.commit_group;")
#define CP_WAIT(n)  asm volatile("cp.async.wait_group %0;" :: "n"(n))

/* ------------------------------------------------------------------ */
/* pre-pass kernels                                                   */
/* ------------------------------------------------------------------ */
__global__ void cvt_pack_h2(const float* __restrict__ in,
                            uint32_t* __restrict__ out, int n2)
{
    int i = blockIdx.x * blockDim.x + threadIdx.x;
    if (i < n2) {
        float2 v = ((const float2*)in)[i];
        out[i] = pack_h2(v.x, v.y);
    }
}

__global__ void cvt_wT_h2(const float* __restrict__ w,
                          uint32_t* __restrict__ outT, int N)
{
    __shared__ uint32_t tile[32][33];
    const int k20 = blockIdx.y * 32, n0 = blockIdx.x * 32;
    for (int r = threadIdx.y; r < 32; r += 8) {
        int k2 = k20 + r;
        int n  = n0 + threadIdx.x;
        tile[r][threadIdx.x] =
            pack_h2(w[(size_t)(2 * k2) * N + n], w[(size_t)(2 * k2 + 1) * N + n]);
    }
    __syncthreads();
    for (int r = threadIdx.y; r < 32; r += 8) {
        int n  = n0 + r;
        int k2 = k20 + threadIdx.x;
        outT[(size_t)n * K2 + k2] = tile[threadIdx.x][r];
    }
}

/* ------------------------------------------------------------------ */
/* FP16 GEMM (r11 structure: single-buffer, plain LDG — proven).      */
/* C = A @ B + bias. A:[m][k/2], BT:[n][k/2]. CTA 128x128, K-tile 64. */
/* ------------------------------------------------------------------ */
#define GS 36   /* u32 stride: frag bank = 4*gid + tig, conflict-free */

__global__ __launch_bounds__(256, 2) void gemm_h(
    const uint32_t* __restrict__ A, const uint32_t* __restrict__ BT,
    const float* __restrict__ bias, uint32_t* __restrict__ C,
    int M, int N, int cvt_out)
{
    __shared__ uint32_t As[128 * GS];
    __shared__ uint32_t Bs[128 * GS];

    const int tid  = threadIdx.x;
    const int lane = tid & 31, wid = tid >> 5;
    const int gid  = lane >> 2, tig = lane & 3;
    const int wm   = (wid >> 2) * 64;
    const int wn   = (wid & 3) * 32;
    const int rowBlk = blockIdx.y * 128;
    const int colBlk = blockIdx.x * 128;

    float acc[4][4][4];
    #pragma unroll
    for (int i = 0; i < 4; i++)
        #pragma unroll
        for (int j = 0; j < 4; j++)
            #pragma unroll
            for (int r = 0; r < 4; r++) acc[i][j][r] = 0.0f;

    for (int t = 0; t < 12; t++) {
        const int k0 = t * 32;
        #pragma unroll
        for (int l = 0; l < 4; l++) {
            int f = tid + l * 256;
            int r = f >> 3, c4 = (f & 7) * 4;
            *(uint4*)&As[r * GS + c4] =
                *(const uint4*)&A[(size_t)(rowBlk + r) * K2 + k0 + c4];
        }
        #pragma unroll
        for (int l = 0; l < 4; l++) {
            int f = tid + l * 256;
            int r = f >> 3, c4 = (f & 7) * 4;
            *(uint4*)&Bs[r * GS + c4] =
                *(const uint4*)&BT[(size_t)(colBlk + r) * K2 + k0 + c4];
        }
        __syncthreads();

        #pragma unroll
        for (int ks = 0; ks < 4; ks++) {
            const int k = ks * 8;
            uint32_t af[4][4], bf[4][2];
            #pragma unroll
            for (int mf = 0; mf < 4; mf++) {
                int m = wm + mf * 16;
                af[mf][0] = As[(m + gid) * GS + k + tig];
                af[mf][1] = As[(m + gid + 8) * GS + k + tig];
                af[mf][2] = As[(m + gid) * GS + k + tig + 4];
                af[mf][3] = As[(m + gid + 8) * GS + k + tig + 4];
            }
            #pragma unroll
            for (int nf = 0; nf < 4; nf++) {
                int n = wn + nf * 8;
                bf[nf][0] = Bs[(n + gid) * GS + k + tig];
                bf[nf][1] = Bs[(n + gid) * GS + k + tig + 4];
            }
            #pragma unroll
            for (int mf = 0; mf < 4; mf++)
                #pragma unroll
                for (int nf = 0; nf < 4; nf++)
                    mma16(acc[mf][nf], af[mf], bf[nf][0], bf[nf][1]);
        }
        __syncthreads();
    }

    /* epilogue: + bias */
    #pragma unroll
    for (int mf = 0; mf < 4; mf++) {
        int row0 = rowBlk + wm + mf * 16 + gid;
        #pragma unroll
        for (int nf = 0; nf < 4; nf++) {
            int col = colBlk + wn + nf * 8 + 2 * tig;
            float2 bv = *(const float2*)&bias[col];
            float v00 = acc[mf][nf][0] + bv.x, v01 = acc[mf][nf][1] + bv.y;
            float v10 = acc[mf][nf][2] + bv.x, v11 = acc[mf][nf][3] + bv.y;
            if (cvt_out) {
                C[(size_t)row0 * (N / 2) + col / 2]       = pack_h2(v00, v01);
                C[(size_t)(row0 + 8) * (N / 2) + col / 2] = pack_h2(v10, v11);
            } else {
                float* Cf = (float*)C;
                float2 o0; o0.x = v00; o0.y = v01;
                float2 o1; o1.x = v10; o1.y = v11;
                *(float2*)&Cf[(size_t)row0 * N + col]       = o0;
                *(float2*)&Cf[(size_t)(row0 + 8) * N + col] = o1;
            }
        }
    }
}

/* ------------------------------------------------------------------ */
/* FP16 flash attention: 3-stage cp.async K/V pipeline, reg-resident  */
/* P, h2 ex2, l via ones-MMA. CTA per (b,h,128 queries), 8 warps.     */
/* smem: 3 stages of [K][V], each 128*GS u32.                         */
/* ------------------------------------------------------------------ */
#define A_STG (2 * 128 * GS)        /* one stage (K+V), u32 */
#define A_STGB (A_STG * 4)
#define ATT_SMEM (3 * A_STGB)       /* 110592 B */
#define N_KT (SEQ_T / 128)          /* 16 key tiles */
#define SCALE_LOG2E 0.18033688f     /* 0.125 * log2(e) */
#define ONE2 0x3C003C00u

__global__ __launch_bounds__(256, 2) void attn_h(
    const uint32_t* __restrict__ qkv, uint32_t* __restrict__ outp)
{
    extern __shared__ uint32_t sm[];
    const uint32_t smb = (uint32_t)__cvta_generic_to_shared(sm);

    const int tid  = threadIdx.x;
    const int lane = tid & 31, wid = tid >> 5;
    const int gid  = lane >> 2, tig = lane & 3;
    const int g = lane >> 3, lr = lane & 7;
    const int q0 = blockIdx.x * 128;
    const int h  = blockIdx.y;
    const int b  = blockIdx.z;
    const uint32_t* base = qkv + (size_t)b * SEQ_T * (QKV_N / 2) + h * (HD / 2);

    const uint32_t loff = ((g & 1) * 8 + lr) * (GS * 4) + (g >> 1) * 16;
    const int lr8 = tid >> 3, lc4 = (tid & 7) * 4;

    /* K/V tile loader: 128-key tile t -> stage s */
    auto load_kv = [&](int t, int s) {
        const uint32_t Kb = smb + s * A_STGB;
        const uint32_t Vb = Kb + 128 * GS * 4;
        #pragma unroll
        for (int l = 0; l < 4; l++) {
            int r = lr8 + l * 32;
            size_t rb = (size_t)(t * 128 + r) * (QKV_N / 2) + lc4;
            cpa16(Kb + (r * GS + lc4) * 4, &base[rb + EMBED / 2]);
            cpa16(Vb + (r * GS + lc4) * 4, &base[rb + EMBED]);
        }
        CP_COMMIT();
    };

    /* prologue: tiles 0,1 -> stages 0,1 (async); Q staged in stage-2 K */
    load_kv(0, 0);
    load_kv(1, 1);
    uint32_t* Qst = sm + 2 * A_STG;   /* stage-2 K area */
    const __half2 qs = __float2half2_rn(SCALE_LOG2E);
    for (int f = tid; f < 128 * 8; f += 256) {
        int r = f >> 3, c4 = (f & 7) * 4;
        uint4 v = *(const uint4*)&base[(size_t)(q0 + r) * (QKV_N / 2) + c4];
        uint32_t* pv = (uint32_t*)&v;
        #pragma unroll
        for (int j = 0; j < 4; j++) {
            __half2 hv = __hmul2(*(__half2*)&pv[j], qs);
            pv[j] = *(uint32_t*)&hv;
        }
        *(uint4*)&Qst[r * GS + c4] = v;
    }
    __syncthreads();

    uint32_t qa[4][4];
    #pragma unroll
    for (int ks = 0; ks < 4; ks++)
        ldsm4(qa[ks], smb + 2 * A_STGB + (wid * 16) * (GS * 4) + loff + ks * 32);

    float o[8][4], lc[4];
    #pragma unroll
    for (int nf = 0; nf < 8; nf++)
        #pragma unroll
        for (int r = 0; r < 4; r++) o[nf][r] = 0.0f;
    #pragma unroll
    for (int r = 0; r < 4; r++) lc[r] = 0.0f;

    for (int t = 0; t < N_KT; t++) {
        if (t < N_KT - 1) { CP_WAIT(1); } else { CP_WAIT(0); }
        __syncthreads();   /* tile t visible; all warps done with stage (t+2)%3
                              (compute t-1 finished; Q frags pulled before t=0) */
        if (t + 2 < N_KT) load_kv(t + 2, (t + 2) % 3);

        const uint32_t Ksa = smb + (t % 3) * A_STGB;
        const uint32_t Vsa = Ksa + 128 * GS * 4;

        #pragma unroll
        for (int half = 0; half < 2; half++) {
            /* S = Q K^T */
            float s[8][4];
            #pragma unroll
            for (int nf = 0; nf < 8; nf++)
                #pragma unroll
                for (int r = 0; r < 4; r++) s[nf][r] = 0.0f;

            #pragma unroll
            for (int ks = 0; ks < 4; ks++) {
                #pragma unroll
                for (int np = 0; np < 4; np++) {
                    uint32_t kb[4];
                    ldsm4(kb, Ksa + (half * 64 + np * 16) * (GS * 4) + loff + ks * 32);
                    mma16(s[2 * np],     qa[ks], kb[0], kb[2]);
                    mma16(s[2 * np + 1], qa[ks], kb[1], kb[3]);
                }
            }

            /* P = 2^S (pack then f16x2 ex2); O += P V; l += P 1 */
            #pragma unroll
            for (int ks = 0; ks < 4; ks++) {
                uint32_t pa[4];
                pa[0] = h2ex2(pack_h2(s[2 * ks][0],     s[2 * ks][1]));
                pa[1] = h2ex2(pack_h2(s[2 * ks][2],     s[2 * ks][3]));
                pa[2] = h2ex2(pack_h2(s[2 * ks + 1][0], s[2 * ks + 1][1]));
                pa[3] = h2ex2(pack_h2(s[2 * ks + 1][2], s[2 * ks + 1][3]));

                mma16(lc, pa, ONE2, ONE2);

                const uint32_t arow = Vsa + (half * 64 + ks * 16) * (GS * 4) + loff;
                #pragma unroll
                for (int np = 0; np < 4; np++) {
                    uint32_t vb[4];
                    ldsm4t(vb, arow + np * 32);
                    mma16(o[2 * np],     pa, vb[0], vb[1]);
                    mma16(o[2 * np + 1], pa, vb[2], vb[3]);
                }
            }
        }
    }

    float i0 = 1.0f / lc[0], i1 = 1.0f / lc[2];
    size_t row0 = (size_t)b * SEQ_T + q0 + wid * 16 + gid;
    #pragma unroll
    for (int nf = 0; nf < 8; nf++) {
        int c2 = h * (HD / 2) + nf * 4 + tig;
        outp[row0 * (EMBED / 2) + c2]       = pack_h2(o[nf][0] * i0, o[nf][1] * i0);
        outp[(row0 + 8) * (EMBED / 2) + c2] = pack_h2(o[nf][2] * i1, o[nf][3] * i1);
    }
}

/* ------------------------------------------------------------------ */
extern "C" void kernel_launch(void* const* d_in, const int* in_sizes, int n_in,
                              void* d_out, int out_size)
{
    (void)in_sizes; (void)n_in; (void)out_size;
    const float* x      = (const float*)d_in[0];
    const float* w_qkv  = (const float*)d_in[1];
    const float* b_qkv  = (const float*)d_in[2];
    const float* w_proj = (const float*)d_in[3];
    const float* b_proj = (const float*)d_in[4];
    uint32_t* out = (uint32_t*)d_out;

    uint32_t *qkvp, *attnp, *xh, *wqkvT, *wprjT;
    cudaGetSymbolAddress((void**)&qkvp,  g_qkv);
    cudaGetSymbolAddress((void**)&attnp, g_attn);
    cudaGetSymbolAddress((void**)&xh,    g_xh);
    cudaGetSymbolAddress((void**)&wqkvT, g_wqkvT);
    cudaGetSymbolAddress((void**)&wprjT, g_wprjT);

    cudaFuncSetAttribute(attn_h,
                         cudaFuncAttributeMaxDynamicSharedMemorySize, ATT_SMEM);

    /* 0) pre-pass: pack x, transpose+pack weights */
    {
        int n2 = M_ROWS * K2;
        cvt_pack_h2<<<(n2 + 255) / 256, 256>>>(x, xh, n2);
        cvt_wT_h2<<<dim3(QKV_N / 32, K2 / 32), dim3(32, 8)>>>(w_qkv, wqkvT, QKV_N);
        cvt_wT_h2<<<dim3(EMBED / 32, K2 / 32), dim3(32, 8)>>>(w_proj, wprjT, EMBED);
    }

    /* 1) QKV GEMM + bias -> half2 */
    gemm_h<<<dim3(QKV_N / 128, M_ROWS / 128), 256>>>(
        xh, wqkvT, b_qkv, qkvp, M_ROWS, QKV_N, 1);

    /* 2) attention -> half2 */
    attn_h<<<dim3(SEQ_T / 128, HEADS, BATCH), 256, ATT_SMEM>>>(qkvp, attnp);

    /* 3) projection GEMM + bias -> f32 out */
    gemm_h<<<dim3(EMBED / 128, M_ROWS / 128), 256>>>(
        attnp, wprjT, b_proj, out, M_ROWS, EMBED, 0);
}

// round 17
// speedup vs baseline: 1.0419x; 1.0419x over previous
#include <cuda_runtime.h>
#include <cuda_fp16.h>
#include <math.h>
#include <stdint.h>

#define EMBED    768
#define SEQ_T    2048
#define BATCH    4
#define HEADS    12
#define HD       64
#define M_ROWS   (BATCH * SEQ_T)     /* 8192 */
#define QKV_N    (3 * EMBED)         /* 2304 */
#define K2       (EMBED / 2)         /* 384 u32 per k-row */

/* scratch — all fp16 payloads stored as uint32 (half2) */
__device__ uint32_t g_qkv  [(size_t)M_ROWS * (QKV_N / 2)];
__device__ uint32_t g_attn [(size_t)M_ROWS * (EMBED / 2)];
__device__ uint32_t g_xh   [(size_t)M_ROWS * K2];
__device__ uint32_t g_wqkvT[(size_t)QKV_N * K2];
__device__ uint32_t g_wprjT[(size_t)EMBED * K2];

/* ---------------- helpers ---------------- */
__device__ __forceinline__ uint32_t pack_h2(float lo, float hi) {
    __half2 h = __floats2half2_rn(lo, hi);
    return *(uint32_t*)&h;
}
__device__ __forceinline__ uint32_t h2ex2(uint32_t x) {
    uint32_t r;
    asm("ex2.approx.f16x2 %0, %1;" : "=r"(r) : "r"(x));
    return r;
}
__device__ __forceinline__ void mma16(float c[4], const uint32_t a[4], const uint32_t b0, const uint32_t b1) {
    asm volatile(
        "mma.sync.aligned.m16n8k16.row.col.f32.f16.f16.f32 "
        "{%0,%1,%2,%3}, {%4,%5,%6,%7}, {%8,%9}, {%0,%1,%2,%3};"
        : "+f"(c[0]), "+f"(c[1]), "+f"(c[2]), "+f"(c[3])
        : "r"(a[0]), "r"(a[1]), "r"(a[2]), "r"(a[3]), "r"(b0), "r"(b1));
}
__device__ __forceinline__ void ldsm4(uint32_t r[4], uint32_t saddr) {
    asm volatile(
        "ldmatrix.sync.aligned.m8n8.x4.shared.b16 {%0,%1,%2,%3}, [%4];"
        : "=r"(r[0]), "=r"(r[1]), "=r"(r[2]), "=r"(r[3]) : "r"(saddr));
}
__device__ __forceinline__ void ldsm4t(uint32_t r[4], uint32_t saddr) {
    asm volatile(
        "ldmatrix.sync.aligned.m8n8.x4.trans.shared.b16 {%0,%1,%2,%3}, [%4];"
        : "=r"(r[0]), "=r"(r[1]), "=r"(r[2]), "=r"(r[3]) : "r"(saddr));
}
__device__ __forceinline__ void cpa16(uint32_t dst, const void* src) {
    asm volatile("cp.async.ca.shared.global [%0], [%1], 16;"
                 :: "r"(dst), "l"(src));
}
#define CP_COMMIT() asm volatile("cp.async.commit_group;")
#define CP_WAIT(n)  asm volatile("cp.async.wait_group %0;" :: "n"(n))

/* ------------------------------------------------------------------ */
/* pre-pass kernels                                                   */
/* ------------------------------------------------------------------ */
__global__ void cvt_pack_h2(const float* __restrict__ in,
                            uint32_t* __restrict__ out, int n2)
{
    int i = blockIdx.x * blockDim.x + threadIdx.x;
    if (i < n2) {
        float2 v = ((const float2*)in)[i];
        out[i] = pack_h2(v.x, v.y);
    }
}

__global__ void cvt_wT_h2(const float* __restrict__ w,
                          uint32_t* __restrict__ outT, int N)
{
    __shared__ uint32_t tile[32][33];
    const int k20 = blockIdx.y * 32, n0 = blockIdx.x * 32;
    for (int r = threadIdx.y; r < 32; r += 8) {
        int k2 = k20 + r;
        int n  = n0 + threadIdx.x;
        tile[r][threadIdx.x] =
            pack_h2(w[(size_t)(2 * k2) * N + n], w[(size_t)(2 * k2 + 1) * N + n]);
    }
    __syncthreads();
    for (int r = threadIdx.y; r < 32; r += 8) {
        int n  = n0 + r;
        int k2 = k20 + threadIdx.x;
        outT[(size_t)n * K2 + k2] = tile[threadIdx.x][r];
    }
}

/* ------------------------------------------------------------------ */
/* FP16 GEMM (proven best: single smem buffer, plain LDG).            */
/* C = A @ B + bias. A:[m][k/2], BT:[n][k/2]. CTA 128x128, K-tile 64. */
/* ------------------------------------------------------------------ */
#define GS 36   /* u32 stride: frag bank = 4*gid + tig, conflict-free */

__global__ __launch_bounds__(256, 2) void gemm_h(
    const uint32_t* __restrict__ A, const uint32_t* __restrict__ BT,
    const float* __restrict__ bias, uint32_t* __restrict__ C,
    int M, int N, int cvt_out)
{
    __shared__ uint32_t As[128 * GS];
    __shared__ uint32_t Bs[128 * GS];

    const int tid  = threadIdx.x;
    const int lane = tid & 31, wid = tid >> 5;
    const int gid  = lane >> 2, tig = lane & 3;
    const int wm   = (wid >> 2) * 64;
    const int wn   = (wid & 3) * 32;
    const int rowBlk = blockIdx.y * 128;
    const int colBlk = blockIdx.x * 128;

    float acc[4][4][4];
    #pragma unroll
    for (int i = 0; i < 4; i++)
        #pragma unroll
        for (int j = 0; j < 4; j++)
            #pragma unroll
            for (int r = 0; r < 4; r++) acc[i][j][r] = 0.0f;

    for (int t = 0; t < 12; t++) {
        const int k0 = t * 32;
        #pragma unroll
        for (int l = 0; l < 4; l++) {
            int f = tid + l * 256;
            int r = f >> 3, c4 = (f & 7) * 4;
            *(uint4*)&As[r * GS + c4] =
                *(const uint4*)&A[(size_t)(rowBlk + r) * K2 + k0 + c4];
        }
        #pragma unroll
        for (int l = 0; l < 4; l++) {
            int f = tid + l * 256;
            int r = f >> 3, c4 = (f & 7) * 4;
            *(uint4*)&Bs[r * GS + c4] =
                *(const uint4*)&BT[(size_t)(colBlk + r) * K2 + k0 + c4];
        }
        __syncthreads();

        #pragma unroll
        for (int ks = 0; ks < 4; ks++) {
            const int k = ks * 8;
            uint32_t af[4][4], bf[4][2];
            #pragma unroll
            for (int mf = 0; mf < 4; mf++) {
                int m = wm + mf * 16;
                af[mf][0] = As[(m + gid) * GS + k + tig];
                af[mf][1] = As[(m + gid + 8) * GS + k + tig];
                af[mf][2] = As[(m + gid) * GS + k + tig + 4];
                af[mf][3] = As[(m + gid + 8) * GS + k + tig + 4];
            }
            #pragma unroll
            for (int nf = 0; nf < 4; nf++) {
                int n = wn + nf * 8;
                bf[nf][0] = Bs[(n + gid) * GS + k + tig];
                bf[nf][1] = Bs[(n + gid) * GS + k + tig + 4];
            }
            #pragma unroll
            for (int mf = 0; mf < 4; mf++)
                #pragma unroll
                for (int nf = 0; nf < 4; nf++)
                    mma16(acc[mf][nf], af[mf], bf[nf][0], bf[nf][1]);
        }
        __syncthreads();
    }

    /* epilogue: + bias */
    #pragma unroll
    for (int mf = 0; mf < 4; mf++) {
        int row0 = rowBlk + wm + mf * 16 + gid;
        #pragma unroll
        for (int nf = 0; nf < 4; nf++) {
            int col = colBlk + wn + nf * 8 + 2 * tig;
            float2 bv = *(const float2*)&bias[col];
            float v00 = acc[mf][nf][0] + bv.x, v01 = acc[mf][nf][1] + bv.y;
            float v10 = acc[mf][nf][2] + bv.x, v11 = acc[mf][nf][3] + bv.y;
            if (cvt_out) {
                C[(size_t)row0 * (N / 2) + col / 2]       = pack_h2(v00, v01);
                C[(size_t)(row0 + 8) * (N / 2) + col / 2] = pack_h2(v10, v11);
            } else {
                float* Cf = (float*)C;
                float2 o0; o0.x = v00; o0.y = v01;
                float2 o1; o1.x = v10; o1.y = v11;
                *(float2*)&Cf[(size_t)row0 * N + col]       = o0;
                *(float2*)&Cf[(size_t)(row0 + 8) * N + col] = o1;
            }
        }
    }
}

/* ------------------------------------------------------------------ */
/* FP16 flash attention (proven best: 2-stage cp.async K/V pipeline), */
/* reg-resident P, h2 ex2, l via ones-MMA. CTA per (b,h,128 queries). */
/* smem: [K0][V0][K1][V1], each 128*GS u32. 73728 B -> 2 CTAs/SM.     */
/* ------------------------------------------------------------------ */
#define A_STG (2 * 128 * GS)        /* one stage (K+V), u32 */
#define A_STGB (A_STG * 4)
#define ATT_SMEM (2 * A_STGB)       /* 73728 B */
#define SCALE_LOG2E 0.18033688f     /* 0.125 * log2(e) */
#define ONE2 0x3C003C00u

__global__ __launch_bounds__(256, 2) void attn_h(
    const uint32_t* __restrict__ qkv, uint32_t* __restrict__ outp)
{
    extern __shared__ uint32_t sm[];
    const uint32_t smb = (uint32_t)__cvta_generic_to_shared(sm);

    const int tid  = threadIdx.x;
    const int lane = tid & 31, wid = tid >> 5;
    const int gid  = lane >> 2, tig = lane & 3;
    const int g = lane >> 3, lr = lane & 7;
    const int q0 = blockIdx.x * 128;
    const int h  = blockIdx.y;
    const int b  = blockIdx.z;
    const uint32_t* base = qkv + (size_t)b * SEQ_T * (QKV_N / 2) + h * (HD / 2);

    const uint32_t loff = ((g & 1) * 8 + lr) * (GS * 4) + (g >> 1) * 16;
    const int lr8 = tid >> 3, lc4 = (tid & 7) * 4;

    /* K/V tile loader: 128-key tile t -> stage s */
    auto load_kv = [&](int t, int s) {
        const uint32_t Kb = smb + s * A_STGB;
        const uint32_t Vb = Kb + 128 * GS * 4;
        #pragma unroll
        for (int l = 0; l < 4; l++) {
            int r = lr8 + l * 32;
            size_t rb = (size_t)(t * 128 + r) * (QKV_N / 2) + lc4;
            cpa16(Kb + (r * GS + lc4) * 4, &base[rb + EMBED / 2]);
            cpa16(Vb + (r * GS + lc4) * 4, &base[rb + EMBED]);
        }
        CP_COMMIT();
    };

    /* prologue: tile 0 -> stage 0 (async); Q staged in stage-1 K area */
    load_kv(0, 0);
    uint32_t* Qst = sm + A_STG;
    const __half2 qs = __float2half2_rn(SCALE_LOG2E);
    for (int f = tid; f < 128 * 8; f += 256) {
        int r = f >> 3, c4 = (f & 7) * 4;
        uint4 v = *(const uint4*)&base[(size_t)(q0 + r) * (QKV_N / 2) + c4];
        uint32_t* pv = (uint32_t*)&v;
        #pragma unroll
        for (int j = 0; j < 4; j++) {
            __half2 hv = __hmul2(*(__half2*)&pv[j], qs);
            pv[j] = *(uint32_t*)&hv;
        }
        *(uint4*)&Qst[r * GS + c4] = v;
    }
    __syncthreads();

    uint32_t qa[4][4];
    #pragma unroll
    for (int ks = 0; ks < 4; ks++)
        ldsm4(qa[ks], smb + A_STGB + (wid * 16) * (GS * 4) + loff + ks * 32);

    float o[8][4], lc[4];
    #pragma unroll
    for (int nf = 0; nf < 8; nf++)
        #pragma unroll
        for (int r = 0; r < 4; r++) o[nf][r] = 0.0f;
    #pragma unroll
    for (int r = 0; r < 4; r++) lc[r] = 0.0f;

    for (int t = 0; t < SEQ_T / 128; t++) {
        const int st = t & 1;
        CP_WAIT(0);
        __syncthreads();   /* tile t visible; prior readers of st^1 done; Q frags pulled */
        if (t + 1 < SEQ_T / 128) load_kv(t + 1, st ^ 1);

        const uint32_t Ksa = smb + st * A_STGB;
        const uint32_t Vsa = Ksa + 128 * GS * 4;

        #pragma unroll
        for (int half = 0; half < 2; half++) {
            /* S = Q K^T */
            float s[8][4];
            #pragma unroll
            for (int nf = 0; nf < 8; nf++)
                #pragma unroll
                for (int r = 0; r < 4; r++) s[nf][r] = 0.0f;

            #pragma unroll
            for (int ks = 0; ks < 4; ks++) {
                #pragma unroll
                for (int np = 0; np < 4; np++) {
                    uint32_t kb[4];
                    ldsm4(kb, Ksa + (half * 64 + np * 16) * (GS * 4) + loff + ks * 32);
                    mma16(s[2 * np],     qa[ks], kb[0], kb[2]);
                    mma16(s[2 * np + 1], qa[ks], kb[1], kb[3]);
                }
            }

            /* P = 2^S (pack then f16x2 ex2); O += P V; l += P 1 */
            #pragma unroll
            for (int ks = 0; ks < 4; ks++) {
                uint32_t pa[4];
                pa[0] = h2ex2(pack_h2(s[2 * ks][0],     s[2 * ks][1]));
                pa[1] = h2ex2(pack_h2(s[2 * ks][2],     s[2 * ks][3]));
                pa[2] = h2ex2(pack_h2(s[2 * ks + 1][0], s[2 * ks + 1][1]));
                pa[3] = h2ex2(pack_h2(s[2 * ks + 1][2], s[2 * ks + 1][3]));

                mma16(lc, pa, ONE2, ONE2);

                const uint32_t arow = Vsa + (half * 64 + ks * 16) * (GS * 4) + loff;
                #pragma unroll
                for (int np = 0; np < 4; np++) {
                    uint32_t vb[4];
                    ldsm4t(vb, arow + np * 32);
                    mma16(o[2 * np],     pa, vb[0], vb[1]);
                    mma16(o[2 * np + 1], pa, vb[2], vb[3]);
                }
            }
        }
    }

    float i0 = 1.0f / lc[0], i1 = 1.0f / lc[2];
    size_t row0 = (size_t)b * SEQ_T + q0 + wid * 16 + gid;
    #pragma unroll
    for (int nf = 0; nf < 8; nf++) {
        int c2 = h * (HD / 2) + nf * 4 + tig;
        outp[row0 * (EMBED / 2) + c2]       = pack_h2(o[nf][0] * i0, o[nf][1] * i0);
        outp[(row0 + 8) * (EMBED / 2) + c2] = pack_h2(o[nf][2] * i1, o[nf][3] * i1);
    }
}

/* ------------------------------------------------------------------ */
extern "C" void kernel_launch(void* const* d_in, const int* in_sizes, int n_in,
                              void* d_out, int out_size)
{
    (void)in_sizes; (void)n_in; (void)out_size;
    const float* x      = (const float*)d_in[0];
    const float* w_qkv  = (const float*)d_in[1];
    const float* b_qkv  = (const float*)d_in[2];
    const float* w_proj = (const float*)d_in[3];
    const float* b_proj = (const float*)d_in[4];
    uint32_t* out = (uint32_t*)d_out;

    uint32_t *qkvp, *attnp, *xh, *wqkvT, *wprjT;
    cudaGetSymbolAddress((void**)&qkvp,  g_qkv);
    cudaGetSymbolAddress((void**)&attnp, g_attn);
    cudaGetSymbolAddress((void**)&xh,    g_xh);
    cudaGetSymbolAddress((void**)&wqkvT, g_wqkvT);
    cudaGetSymbolAddress((void**)&wprjT, g_wprjT);

    cudaFuncSetAttribute(attn_h,
                         cudaFuncAttributeMaxDynamicSharedMemorySize, ATT_SMEM);

    /* 0) pre-pass: pack x, transpose+pack weights */
    {
        int n2 = M_ROWS * K2;
        cvt_pack_h2<<<(n2 + 255) / 256, 256>>>(x, xh, n2);
        cvt_wT_h2<<<dim3(QKV_N / 32, K2 / 32), dim3(32, 8)>>>(w_qkv, wqkvT, QKV_N);
        cvt_wT_h2<<<dim3(EMBED / 32, K2 / 32), dim3(32, 8)>>>(w_proj, wprjT, EMBED);
    }

    /* 1) QKV GEMM + bias -> half2 */
    gemm_h<<<dim3(QKV_N / 128, M_ROWS / 128), 256>>>(
        xh, wqkvT, b_qkv, qkvp, M_ROWS, QKV_N, 1);

    /* 2) attention -> half2 */
    attn_h<<<dim3(SEQ_T / 128, HEADS, BATCH), 256, ATT_SMEM>>>(qkvp, attnp);

    /* 3) projection GEMM + bias -> f32 out */
    gemm_h<<<dim3(EMBED / 128, M_ROWS / 128), 256>>>(
        attnp, wprjT, b_proj, out, M_ROWS, EMBED, 0);
}